// round 13
// baseline (speedup 1.0000x reference)
#include <cuda_runtime.h>
#include <cuda_bf16.h>

#define R_    512
#define C_    256
#define H_    200
#define W_    200
#define OUTK  7
#define HW_   (H_*W_)
#define CHUNK 32   // channels per block; warp g owns {g, g+8, g+16, g+24}

// ---------------------------------------------------------------------------
// Warp-serial-oy RoIAlign. Grid (512 roi, 8 chunk), chunk slowest -> per-
// phase feature set (~17 MB) L2-resident (DRAM ~157 MB compulsory).
//
// Each warp walks all 7 oy bins SERIALLY for its 4 channels. Successive oy
// bins share ~35% of their patch rows, and since the same warp (same SM,
// same L1D) re-requests them back-to-back, those become L1 hits (39 cyc)
// instead of separate L2 round-trips (234 cyc) -- the R8 layout spread the
// 7 oy over different SMs and paid L2 latency for every duplicate.
//
// Phase 1: warp 0 -> 28-entry x-tap table. Warp 1 -> per-oy dense y-weights:
// lane = oy*4 + slot; intra-group shfls gather the 4 taps of this oy, each
// slot sums the tap weights landing on row rbase+slot. All shfls full-warp
// convergent (lanes 28..31 run with dummy group, never write).
//
// Phase 2: per oy: read rbase/rcnt/dw from SMEM (uniform), rcnt-templated
// 4-channel gather (16 LDGs max, proven R8 body), 4-lane shfl reduce,
// lanes {0,4,..,24} store out[r][c][oy][0..6].
// ---------------------------------------------------------------------------

template<int K>
__device__ __forceinline__ void accum4(
    const float* __restrict__ fb, const int off[4], const float dw[4],
    float b[4])
{
    float v[4][K];
    #pragma unroll
    for (int g = 0; g < 4; g++) {
        const float* f = fb + g * (8 * HW_);
        #pragma unroll
        for (int j = 0; j < K; j++)
            v[g][j] = __ldg(f + off[j]);
    }
    #pragma unroll
    for (int g = 0; g < 4; g++) {
        float a = 0.f;
        #pragma unroll
        for (int j = 0; j < K; j++)
            a += dw[j] * v[g][j];
        b[g] = a;
    }
}

__global__ __launch_bounds__(256) void roialign_kernel(
    const float* __restrict__ feat, const float* __restrict__ rois,
    float* __restrict__ out)
{
    int r   = blockIdx.x;
    int ch0 = blockIdx.y * CHUNK;

    __shared__ int   s_xi[28];
    __shared__ float s_xw[28];
    __shared__ float s_dw[7 * 4];    // dense y-weights per oy
    __shared__ int   s_rb[7];        // row base per oy
    __shared__ int   s_rc[7];        // row count per oy (1..4)
    __shared__ int   s_boff;

    int tid  = threadIdx.x;
    int lane = tid & 31;
    int warp = tid >> 5;

    if (warp < 2) {                  // warp0: x-taps, warp1: y-weights
        const float* ro = rois + r * 5;
        bool isx = (warp == 0);
        float p1 = (isx ? ro[1] : ro[2]) * 0.25f;
        float p2 = (isx ? ro[3] : ro[4]) * 0.25f;
        float bin = fmaxf(p2 - p1, 1.0f) * (1.0f / (float)OUTK);

        int t   = min(lane, 27);
        int o   = t >> 2;
        int s   = (t >> 1) & 1;
        int tap = t & 1;
        float y = p1 + ((float)o + ((float)s + 0.5f) * 0.5f) * bin;
        bool valid = (y >= -1.0f) && (y <= 200.0f);
        float yc = fminf(fmaxf(y, 0.0f), 199.0f);
        int   yl = (int)floorf(yc);
        int   yh = min(yl + 1, 199);
        float fl = yc - (float)yl;
        float wv = tap ? fl : (1.0f - fl);
        if (!valid) wv = 0.0f;
        int   iv = tap ? yh : yl;

        if (isx) {
            if (lane < 28) { s_xi[lane] = iv; s_xw[lane] = wv; }
        } else {
            // Gather this oy-group's 4 taps via intra-group shfl (convergent).
            int base = lane & ~3;
            int   i0 = __shfl_sync(0xffffffffu, iv, base);
            int   i1 = __shfl_sync(0xffffffffu, iv, base + 1);
            int   i2 = __shfl_sync(0xffffffffu, iv, base + 2);
            int   i3 = __shfl_sync(0xffffffffu, iv, base + 3);
            float w0 = __shfl_sync(0xffffffffu, wv, base);
            float w1 = __shfl_sync(0xffffffffu, wv, base + 1);
            float w2 = __shfl_sync(0xffffffffu, wv, base + 2);
            float w3 = __shfl_sync(0xffffffffu, wv, base + 3);
            if (lane < 28) {
                int rb   = i0;                       // sorted: i0 min, i3 max
                int slot = lane & 3;
                float dw = ((i0 - rb) == slot ? w0 : 0.f)
                         + ((i1 - rb) == slot ? w1 : 0.f)
                         + ((i2 - rb) == slot ? w2 : 0.f)
                         + ((i3 - rb) == slot ? w3 : 0.f);
                s_dw[o * 4 + slot] = dw;
                if (slot == 0) { s_rb[o] = rb; s_rc[o] = i3 - rb + 1; }
            }
        }
        if (tid == 0) s_boff = (int)ro[0] * (C_ * HW_);
    }
    __syncthreads();

    int l    = min(lane, 27);
    int   xi = s_xi[l];
    float xw = s_xw[l] * 0.25f;      // fold S*S mean
    const float* fb = feat + s_boff + (size_t)(ch0 + warp) * HW_;

    int  ox      = l >> 2;
    bool doStore = (lane < 28) && ((lane & 3) == 0);
    float* ob    = out + ((size_t)r * C_ + ch0 + warp) * (OUTK * OUTK) + ox;

    #pragma unroll
    for (int oy = 0; oy < 7; oy++) {
        int rb = s_rb[oy];
        int rc = s_rc[oy];
        float dw[4] = { s_dw[oy * 4], s_dw[oy * 4 + 1],
                        s_dw[oy * 4 + 2], s_dw[oy * 4 + 3] };
        int off[4];
        #pragma unroll
        for (int j = 0; j < 4; j++)
            off[j] = (rb + j) * W_ + xi;

        float b[4];
        switch (rc) {                // uniform per warp
            case 1:  accum4<1>(fb, off, dw, b); break;
            case 2:  accum4<2>(fb, off, dw, b); break;
            case 3:  accum4<3>(fb, off, dw, b); break;
            default: accum4<4>(fb, off, dw, b); break;
        }

        #pragma unroll
        for (int g = 0; g < 4; g++) {
            float v = b[g] * xw;
            v += __shfl_xor_sync(0xffffffffu, v, 1);
            v += __shfl_xor_sync(0xffffffffu, v, 2);
            if (doStore) ob[(size_t)(g * 8) * (OUTK * OUTK) + oy * OUTK] = v;
        }
    }
}

extern "C" void kernel_launch(void* const* d_in, const int* in_sizes, int n_in,
                              void* d_out, int out_size) {
    const float* feat = (const float*)d_in[0];
    const float* rois = (const float*)d_in[1];
    if (n_in >= 2 && in_sizes[0] == R_ * 5) {  // defensive against input order
        feat = (const float*)d_in[1];
        rois = (const float*)d_in[0];
    }
    float* out = (float*)d_out;

    dim3 grid(R_, C_ / CHUNK);       // chunk slowest -> L2 phase blocking
    roialign_kernel<<<grid, 256>>>(feat, rois, out);
}

// round 14
// speedup vs baseline: 1.0735x; 1.0735x over previous
#include <cuda_runtime.h>
#include <cuda_bf16.h>

#define R_    512
#define C_    256
#define H_    200
#define W_    200
#define OUTK  7
#define HW_   (H_*W_)
#define CHUNK 32   // channels per block; warp g owns {g, g+8, g+16, g+24}
#define OSZ   (OUTK * OUTK)   // 49

// ---------------------------------------------------------------------------
// Serial-oy RoIAlign + SMEM-staged coalesced stores.
// Grid (512 roi, 8 chunk), chunk slowest -> per-phase feature set (~17 MB)
// L2-resident (DRAM ~157 MB compulsory).
//
// Loads (proven R13 body): each warp walks the 7 oy bins serially for its 4
// channels; dense y-weights over the contiguous row span (rcnt<=4) keep
// row-loads minimal, and consecutive oy bins re-hit overlapping rows in L1D.
//
// NEW: stores. The old per-oy STG.32 had 7 active lanes at stride 196B =
// 7 sectors per store -> 1568 store-wavefronts per block (HALF of all L1
// work). Now lanes stage results in s_out[32][49] (conflict-free STS) and
// the block writes the contiguous 1568-float output region with coalesced
// 128B warp stores: 1568 -> 49 store-wavefronts per block (-97%).
// ---------------------------------------------------------------------------

template<int K>
__device__ __forceinline__ void accum4(
    const float* __restrict__ fb, const int off[4], const float dw[4],
    float b[4])
{
    float v[4][K];
    #pragma unroll
    for (int g = 0; g < 4; g++) {
        const float* f = fb + g * (8 * HW_);
        #pragma unroll
        for (int j = 0; j < K; j++)
            v[g][j] = __ldg(f + off[j]);
    }
    #pragma unroll
    for (int g = 0; g < 4; g++) {
        float a = 0.f;
        #pragma unroll
        for (int j = 0; j < K; j++)
            a += dw[j] * v[g][j];
        b[g] = a;
    }
}

__global__ __launch_bounds__(256) void roialign_kernel(
    const float* __restrict__ feat, const float* __restrict__ rois,
    float* __restrict__ out)
{
    int r   = blockIdx.x;
    int ch0 = blockIdx.y * CHUNK;

    __shared__ int   s_xi[28];
    __shared__ float s_xw[28];
    __shared__ float s_dw[7 * 4];    // dense y-weights per oy
    __shared__ int   s_rb[7];        // row base per oy
    __shared__ int   s_rc[7];        // row count per oy (1..4)
    __shared__ int   s_boff;
    __shared__ float s_out[CHUNK * OSZ];   // staged output tile

    int tid  = threadIdx.x;
    int lane = tid & 31;
    int warp = tid >> 5;

    if (warp < 2) {                  // warp0: x-taps, warp1: y-weights
        const float* ro = rois + r * 5;
        bool isx = (warp == 0);
        float p1 = (isx ? ro[1] : ro[2]) * 0.25f;
        float p2 = (isx ? ro[3] : ro[4]) * 0.25f;
        float bin = fmaxf(p2 - p1, 1.0f) * (1.0f / (float)OUTK);

        int t   = min(lane, 27);
        int o   = t >> 2;
        int s   = (t >> 1) & 1;
        int tap = t & 1;
        float y = p1 + ((float)o + ((float)s + 0.5f) * 0.5f) * bin;
        bool valid = (y >= -1.0f) && (y <= 200.0f);
        float yc = fminf(fmaxf(y, 0.0f), 199.0f);
        int   yl = (int)floorf(yc);
        int   yh = min(yl + 1, 199);
        float fl = yc - (float)yl;
        float wv = tap ? fl : (1.0f - fl);
        if (!valid) wv = 0.0f;
        int   iv = tap ? yh : yl;

        if (isx) {
            if (lane < 28) { s_xi[lane] = iv; s_xw[lane] = wv; }
        } else {
            // Gather this oy-group's 4 taps via intra-group shfl (convergent).
            int base = lane & ~3;
            int   i0 = __shfl_sync(0xffffffffu, iv, base);
            int   i1 = __shfl_sync(0xffffffffu, iv, base + 1);
            int   i2 = __shfl_sync(0xffffffffu, iv, base + 2);
            int   i3 = __shfl_sync(0xffffffffu, iv, base + 3);
            float w0 = __shfl_sync(0xffffffffu, wv, base);
            float w1 = __shfl_sync(0xffffffffu, wv, base + 1);
            float w2 = __shfl_sync(0xffffffffu, wv, base + 2);
            float w3 = __shfl_sync(0xffffffffu, wv, base + 3);
            if (lane < 28) {
                int rb   = i0;                       // sorted: i0 min, i3 max
                int slot = lane & 3;
                float dw = ((i0 - rb) == slot ? w0 : 0.f)
                         + ((i1 - rb) == slot ? w1 : 0.f)
                         + ((i2 - rb) == slot ? w2 : 0.f)
                         + ((i3 - rb) == slot ? w3 : 0.f);
                s_dw[o * 4 + slot] = dw;
                if (slot == 0) { s_rb[o] = rb; s_rc[o] = i3 - rb + 1; }
            }
        }
        if (tid == 0) s_boff = (int)ro[0] * (C_ * HW_);
    }
    __syncthreads();

    int l    = min(lane, 27);
    int   xi = s_xi[l];
    float xw = s_xw[l] * 0.25f;      // fold S*S mean
    const float* fb = feat + s_boff + (size_t)(ch0 + warp) * HW_;

    int  ox      = l >> 2;
    bool doStore = (lane < 28) && ((lane & 3) == 0);

    #pragma unroll
    for (int oy = 0; oy < 7; oy++) {
        int rb = s_rb[oy];
        int rc = s_rc[oy];
        float dw[4] = { s_dw[oy * 4], s_dw[oy * 4 + 1],
                        s_dw[oy * 4 + 2], s_dw[oy * 4 + 3] };
        int off[4];
        #pragma unroll
        for (int j = 0; j < 4; j++)
            off[j] = (rb + j) * W_ + xi;

        float b[4];
        switch (rc) {                // uniform per warp
            case 1:  accum4<1>(fb, off, dw, b); break;
            case 2:  accum4<2>(fb, off, dw, b); break;
            case 3:  accum4<3>(fb, off, dw, b); break;
            default: accum4<4>(fb, off, dw, b); break;
        }

        #pragma unroll
        for (int g = 0; g < 4; g++) {
            float v = b[g] * xw;
            v += __shfl_xor_sync(0xffffffffu, v, 1);
            v += __shfl_xor_sync(0xffffffffu, v, 2);
            if (doStore)
                s_out[(warp + g * 8) * OSZ + oy * OUTK + ox] = v;
        }
    }
    __syncthreads();

    // Coalesced writeout: contiguous 1568-float region per (roi, chunk).
    float* ob = out + ((size_t)r * C_ + ch0) * OSZ;
    #pragma unroll
    for (int i = 0; i < (CHUNK * OSZ + 255) / 256; i++) {
        int idx = tid + i * 256;
        if (idx < CHUNK * OSZ)
            ob[idx] = s_out[idx];
    }
}

extern "C" void kernel_launch(void* const* d_in, const int* in_sizes, int n_in,
                              void* d_out, int out_size) {
    const float* feat = (const float*)d_in[0];
    const float* rois = (const float*)d_in[1];
    if (n_in >= 2 && in_sizes[0] == R_ * 5) {  // defensive against input order
        feat = (const float*)d_in[1];
        rois = (const float*)d_in[0];
    }
    float* out = (float*)d_out;

    dim3 grid(R_, C_ / CHUNK);       // chunk slowest -> L2 phase blocking
    roialign_kernel<<<grid, 256>>>(feat, rois, out);
}